// round 13
// baseline (speedup 1.0000x reference)
#include <cuda_runtime.h>
#include <cstdint>

#define HW_ (128 * 128)
static constexpr int IMG = 128;
static constexpr int NB  = 304;
static constexpr size_t BUF_ELEMS = (size_t)NB * 32 * HW_;

// Activation records: CIN u32 per pixel; slot ci = bf16(xh) | bf16(xl)<<16
__device__ uint32_t g_bufA[BUF_ELEMS];
__device__ uint32_t g_bufB[BUF_ELEMS];

__constant__ int c_chidx[19][4] = {
    {1, 8, 19, 20}, {8, 9, 21, 22}, {9, 10, 23, 24}, {1, 11, 25, 26},
    {11, 12, 27, 28}, {12, 13, 29, 30}, {1, 2, 31, 32}, {2, 3, 33, 34},
    {3, 4, 35, 36}, {2, 16, 37, 38}, {1, 5, 39, 40}, {5, 6, 41, 42},
    {6, 7, 43, 44}, {5, 17, 45, 46}, {0, 1, 47, 48}, {0, 14, 49, 50},
    {0, 15, 51, 52}, {14, 16, 53, 54}, {15, 17, 55, 56}
};

typedef unsigned long long u64;

__device__ __forceinline__ u64 pack2(float lo, float hi) {
    u64 r; asm("mov.b64 %0, {%1, %2};" : "=l"(r) : "f"(lo), "f"(hi)); return r;
}
__device__ __forceinline__ void unpack2(u64 v, float& lo, float& hi) {
    asm("mov.b64 {%0, %1}, %2;" : "=f"(lo), "=f"(hi) : "l"(v));
}
__device__ __forceinline__ void ffma2(u64& d, u64 a, u64 b) {
    asm("fma.rn.f32x2 %0, %1, %2, %0;" : "+l"(d) : "l"(a), "l"(b));
}

// bf16 RNE split: v = hi_part + lo_part
__device__ __forceinline__ void bf16split(float v, uint32_t& hi, uint32_t& lo) {
    uint32_t ub = __float_as_uint(v);
    uint32_t hb = (ub + 0x7FFFu + ((ub >> 16) & 1u)) & 0xFFFF0000u;
    hi = hb >> 16;
    float lof = v - __uint_as_float(hb);
    uint32_t ul = __float_as_uint(lof);
    lo = (ul + 0x7FFFu + ((ul >> 16) & 1u)) >> 16;
}
__device__ __forceinline__ uint32_t packpair(float v) {
    uint32_t hi, lo; bf16split(v, hi, lo); return hi | (lo << 16);
}
__device__ __forceinline__ float decpair(uint32_t u) {
    return __uint_as_float(u << 16) + __uint_as_float(u & 0xFFFF0000u);
}

__device__ __forceinline__ void cpasync16(unsigned dst, const void* src, int sz) {
    asm volatile("cp.async.cg.shared.global [%0], [%1], 16, %2;"
                 :: "r"(dst), "l"(src), "r"(sz));
}
__device__ __forceinline__ void cpasync4(unsigned dst, const float* src, int sz) {
    asm volatile("cp.async.ca.shared.global [%0], [%1], 4, %2;"
                 :: "r"(dst), "l"(src), "r"(sz));
}
__device__ __forceinline__ void cpasync_commit() { asm volatile("cp.async.commit_group;"); }
__device__ __forceinline__ void cpasync_wait_all() {
    asm volatile("cp.async.wait_group 0;" ::: "memory");
}

#define SMEM_SWZ(off) ((off) ^ (((off) >> 3) & 0x70))

__device__ __forceinline__ uint32_t smem_u32(const void* p) {
    uint32_t a;
    asm("{ .reg .u64 t; cvta.to.shared.u64 t, %1; cvt.u32.u64 %0, t; }" : "=r"(a) : "l"(p));
    return a;
}
// ldmatrix x4 (baseline PTX, sm_75+)
__device__ __forceinline__ void ldsm4(uint32_t* r, uint32_t addr) {
    asm volatile("ldmatrix.sync.aligned.m8n8.x4.shared.b16 {%0,%1,%2,%3}, [%4];"
                 : "=r"(r[0]), "=r"(r[1]), "=r"(r[2]), "=r"(r[3]) : "r"(addr));
}
// mma.sync bf16 (baseline PTX, sm_80+) -> HMMA
__device__ __forceinline__ void mma_bf16(float* c, const uint32_t* a,
                                         uint32_t b0, uint32_t b1) {
    asm volatile(
        "mma.sync.aligned.m16n8k16.row.col.f32.bf16.bf16.f32 "
        "{%0,%1,%2,%3}, {%4,%5,%6,%7}, {%8,%9}, {%0,%1,%2,%3};"
        : "+f"(c[0]), "+f"(c[1]), "+f"(c[2]), "+f"(c[3])
        : "r"(a[0]), "r"(a[1]), "r"(a[2]), "r"(a[3]), "r"(b0), "r"(b1));
}

// One shared declaration for every dynamic-smem kernel in this TU.
extern __shared__ __align__(1024) unsigned char dynsmem[];

// ---------------------------------------------------------------------------
// HMMA 5x5 conv + relu.  Grid (64 row-pairs, 1, NB), 256 thr (8 warps).
// Warp w: 32 pixels (2 m16 frags) x COUT.  A from swizzled record tile via
// ldmatrix; B per tap [co][2*CIN bf16]; pass0 (wh,wh) = x*wh, pass1 (wl,0)
// = xh*wl.  f32 accumulators in registers across both passes.
// ---------------------------------------------------------------------------
template <int CIN, int COUT>
__global__ __launch_bounds__(256, 1)
void tconv(const uint32_t* __restrict__ in_rec, const float* __restrict__ w,
           const float* __restrict__ bias, uint32_t* __restrict__ out_rec) {
    constexpr int RECB = CIN * 4;                 // bytes per input record
    constexpr int KB   = CIN * 4;                 // bytes per co per tap in B
    constexpr int KS   = CIN / 8;                 // K-steps of 16 bf16
    constexpr int NG   = COUT / 8;                // 8-wide n-groups
    constexpr int A_OFF = 1024;
    constexpr int A_BYTES = 6 * 132 * RECB;
    constexpr int B_OFF = A_OFF + ((A_BYTES + 1023) & ~1023);
    constexpr int U = RECB / 16;                  // 16B units per record

    unsigned char* smem = dynsmem;
    const uint32_t sb = smem_u32(smem);
    const int tid  = threadIdx.x;
    const int wnum = tid >> 5;
    const int lane = tid & 31;
    const int y0   = blockIdx.x * 2;
    const int b    = blockIdx.z;
    const size_t img = (size_t)b * 16384;

    if (tid < COUT) ((float*)smem)[tid] = bias[tid];

    // ---- stage A: rows y0-2..y0+3, 132 px, zfill halo ----
    {
        constexpr int TOT = 6 * 132 * U;
        for (int idx = tid; idx < TOT; idx += 256) {
            int pix = idx / U, u = idx - pix * U;
            int row = pix / 132, xc = pix - row * 132;
            int y = y0 - 2 + row, x = xc - 2;
            bool v = ((unsigned)y < 128u) & ((unsigned)x < 128u);
            const char* src =
                (const char*)(in_rec + (img + (v ? (size_t)(y * 128 + x) : 0)) * CIN) + u * 16;
            unsigned rel = (unsigned)(pix * RECB + u * 16);
            cpasync16(sb + A_OFF + SMEM_SWZ(rel), src, v ? 16 : 0);
        }
        cpasync_commit();
    }

    // ---- B staging (computed bf16 split from fp32 weights) ----
    auto stageB = [&](int pass) {
        constexpr int TOT = 25 * COUT * CIN;      // u32 slots
        for (int i = tid; i < TOT; i += 256) {
            int ci = i % CIN;
            int co = (i / CIN) % COUT;
            int tap = i / (CIN * COUT);
            float wv = w[((size_t)co * CIN + ci) * 25 + tap];
            uint32_t hi, lo;
            bf16split(wv, hi, lo);
            uint32_t val = pass ? lo : (hi | (hi << 16));
            unsigned rel = (unsigned)(tap * (COUT * KB) + co * KB + ci * 4);
            *(uint32_t*)(smem + B_OFF + SMEM_SWZ(rel)) = val;
        }
    };
    stageB(0);
    cpasync_wait_all();
    __syncthreads();

    // per-thread ldmatrix address components (PTX m16n8k16 frag order)
    const int a_px = ((lane >> 3) & 1) * 8 + (lane & 7);   // m0/m1 rows, m2/m3 rows
    const int a_kb = (lane >> 4) * 16;                      // k halves
    const int b_n  = ((lane >> 4) & 1) * 8 + (lane & 7);
    const int b_kb = ((lane >> 3) & 1) * 16;

    float acc[2][NG][4];
#pragma unroll
    for (int f = 0; f < 2; ++f)
#pragma unroll
        for (int g = 0; g < NG; ++g)
#pragma unroll
            for (int i = 0; i < 4; ++i) acc[f][g][i] = 0.0f;

    const uint32_t sbA = sb + A_OFF;
    const uint32_t sbB = sb + B_OFF;
    const int wrow = wnum >> 2;           // output row within pair
    const int wcol = (wnum & 3) * 32;     // x-base of this warp's 32 px

#pragma unroll 1
    for (int pass = 0; pass < 2; ++pass) {
        if (pass == 1) {
            __syncthreads();              // all warps done with pass-0 B
            stageB(1);
            __syncthreads();
        }
#pragma unroll 1
        for (int tap = 0; tap < 25; ++tap) {
            int dy = tap / 5, dx = tap - dy * 5;
            unsigned abase = (unsigned)(((wrow + dy) * 132 + wcol + dx + a_px) * RECB + a_kb);
            unsigned bbase = (unsigned)(tap * (COUT * KB) + b_n * KB + b_kb);
#pragma unroll
            for (int kc = 0; kc < KS; ++kc) {
                uint32_t a0[4], a1[4];
                ldsm4(a0, sbA + SMEM_SWZ(abase + kc * 32));
                ldsm4(a1, sbA + SMEM_SWZ(abase + 16 * RECB + kc * 32));
                uint32_t bf[NG / 2 + 1][4];
#pragma unroll
                for (int gp = 0; gp < NG / 2; ++gp)
                    ldsm4(bf[gp], sbB + SMEM_SWZ(bbase + gp * 16 * KB + kc * 32));
#pragma unroll
                for (int g = 0; g < NG; ++g) {
                    uint32_t br0 = bf[g >> 1][(g & 1) * 2];
                    uint32_t br1 = bf[g >> 1][(g & 1) * 2 + 1];
                    mma_bf16(acc[0][g], a0, br0, br1);
                    mma_bf16(acc[1][g], a1, br0, br1);
                }
            }
        }
    }

    __syncthreads();                      // before reusing B region as scratch

    // ---- epilogue: +bias, relu, pack pairs, smem transpose, coalesced out ----
    {
        const float* sbias = (const float*)smem;
        uint32_t* so = (uint32_t*)(smem + B_OFF);
        constexpr int STR = COUT + 4;     // u32 stride, keeps 16B px alignment
        const int pxb = wnum * 32;
#pragma unroll
        for (int f = 0; f < 2; ++f) {
            int px = pxb + f * 16 + (lane >> 2);
#pragma unroll
            for (int g = 0; g < NG; ++g) {
                int co = g * 8 + (lane & 3) * 2;
                float v0 = fmaxf(acc[f][g][0] + sbias[co], 0.0f);
                float v1 = fmaxf(acc[f][g][1] + sbias[co + 1], 0.0f);
                float v2 = fmaxf(acc[f][g][2] + sbias[co], 0.0f);
                float v3 = fmaxf(acc[f][g][3] + sbias[co + 1], 0.0f);
                so[px * STR + co]           = packpair(v0);
                so[px * STR + co + 1]       = packpair(v1);
                so[(px + 8) * STR + co]     = packpair(v2);
                so[(px + 8) * STR + co + 1] = packpair(v3);
            }
        }
        __syncthreads();

        constexpr int CH = COUT / 4;      // uint4 chunks per pixel
        const int u  = tid & (CH - 1);
        const int pb = tid / CH;
#pragma unroll
        for (int k = 0; k < CH; ++k) {
            int p = pb + k * (256 / CH);
            uint4 val;
            val.x = so[p * STR + u * 4 + 0];
            val.y = so[p * STR + u * 4 + 1];
            val.z = so[p * STR + u * 4 + 2];
            val.w = so[p * STR + u * 4 + 3];
            int y = y0 + (p >> 7), x = p & 127;
            *(uint4*)(out_rec + (img + (size_t)y * 128 + x) * COUT + u * 4) = val;
        }
    }
}

// ---------------------------------------------------------------------------
// Layer 0: FFMA2 5x5 conv with gather (4 -> 16), writes 16-u32 records.
// ---------------------------------------------------------------------------
__global__ __launch_bounds__(256, 3) void conv0(const float* __restrict__ in,
                                                const float* __restrict__ w,
                                                const float* __restrict__ bias,
                                                uint32_t* __restrict__ out) {
    constexpr int CIN = 4, CO = 8;
    constexpr int SW_SZ = CIN * 25 * CO;
    constexpr int TILE  = 36 * 36;
    float* smem = (float*)dynsmem;
    float* s_w  = smem;
    float* s_in = smem + SW_SZ;
    float* s_b  = s_in + 2 * TILE;

    const int tid = threadIdx.x;
    const int tile = blockIdx.x, g = blockIdx.y, b = blockIdx.z;
    const int tile_x = (tile & 3) * 32, tile_y = (tile >> 2) * 32;

    for (int idx = tid; idx < SW_SZ; idx += 256) {
        int co = idx & 7, r = idx >> 3;
        int ci = r / 25, tap = r % 25;
        s_w[idx] = w[((size_t)(g * CO + co) * CIN + ci) * 25 + tap];
    }
    if (tid < CO) s_b[tid] = bias[g * CO + tid];

    int n = b / 19, e = b - n * 19;
    const float* src = in + (size_t)n * 57 * HW_;

    int off[6], szb[6];
#pragma unroll
    for (int k = 0; k < 6; ++k) {
        int idx = tid + k * 256;
        int r = idx / 36, c = idx - r * 36;
        int ih = tile_y + r - 2, iw = tile_x + c - 2;
        bool v = ((unsigned)ih < 128u) && ((unsigned)iw < 128u);
        szb[k] = v ? 4 : 0;
        off[k] = v ? (ih * IMG + iw) : 0;
    }

    const unsigned s_in_b = (unsigned)__cvta_generic_to_shared(s_in);
    const int tx = tid & 31, ty = tid >> 5;

    u64 acc[4][4];
#pragma unroll
    for (int p = 0; p < 4; ++p)
#pragma unroll
        for (int c = 0; c < 4; ++c) acc[p][c] = 0ull;

    auto stage = [&](int ci_n, int bi) {
        const float* sp = src + (size_t)c_chidx[e][ci_n] * HW_;
        unsigned base = s_in_b + (unsigned)(bi * TILE * 4);
#pragma unroll
        for (int k = 0; k < 6; ++k) {
            int idx = tid + k * 256;
            if (k < 5 || tid < (TILE - 5 * 256))
                cpasync4(base + (unsigned)idx * 4u, sp + off[k], szb[k]);
        }
        cpasync_commit();
    };

    stage(0, 0);
    cpasync_wait_all();
    __syncthreads();

    for (int ci = 0; ci < CIN; ++ci) {
        if (ci + 1 < CIN) stage(ci + 1, (ci + 1) & 1);
        const float* cb = s_in + (ci & 1) * TILE;
        const float* wbase = s_w + ci * 25 * CO;
#pragma unroll
        for (int dx = 0; dx < 5; ++dx) {
            u64 dup[8];
#pragma unroll
            for (int j = 0; j < 8; ++j) {
                float v = cb[(ty * 4 + j) * 36 + tx + dx];
                dup[j] = pack2(v, v);
            }
#pragma unroll
            for (int dy = 0; dy < 5; ++dy) {
                const ulonglong2* wr =
                    reinterpret_cast<const ulonglong2*>(wbase + (dy * 5 + dx) * CO);
                ulonglong2 wp0 = wr[0], wp1 = wr[1];
#pragma unroll
                for (int p = 0; p < 4; ++p) {
                    ffma2(acc[p][0], dup[dy + p], wp0.x);
                    ffma2(acc[p][1], dup[dy + p], wp0.y);
                    ffma2(acc[p][2], dup[dy + p], wp1.x);
                    ffma2(acc[p][3], dup[dy + p], wp1.y);
                }
            }
        }
        if (ci + 1 < CIN) {
            cpasync_wait_all();
            __syncthreads();
        }
    }

    // epilogue -> 16-u32 records (slot = g*8 + co)
    const int y0 = tile_y + ty * 4, x = tile_x + tx;
    uint32_t* ob = out + (size_t)b * 16384 * 16 + g * CO;
#pragma unroll
    for (int p = 0; p < 4; ++p) {
        uint32_t* op = ob + (size_t)((y0 + p) * 128 + x) * 16;
#pragma unroll
        for (int c = 0; c < 4; ++c) {
            float v0, v1;
            unpack2(acc[p][c], v0, v1);
            v0 = fmaxf(v0 + s_b[2 * c], 0.0f);
            v1 = fmaxf(v1 + s_b[2 * c + 1], 0.0f);
            op[2 * c]     = packpair(v0);
            op[2 * c + 1] = packpair(v1);
        }
    }
}

// ---------------------------------------------------------------------------
// fused 1x1: 32 -> 128 (relu) -> 2, reads 32-u32 records, writes fp32 output.
// ---------------------------------------------------------------------------
__global__ __launch_bounds__(256) void conv56(const uint32_t* __restrict__ in,
                                              const float* __restrict__ w5,
                                              const float* __restrict__ b5,
                                              const float* __restrict__ w6,
                                              const float* __restrict__ b6,
                                              float* __restrict__ out) {
    __shared__ __align__(16) u64 s_w5[128 * 32];
    __shared__ __align__(16) u64 s_w6[2 * 128];
    __shared__ float s_b5[128];

    const int tid = threadIdx.x;
    const int b   = blockIdx.y;
    const int px0 = blockIdx.x * 512 + tid;

    for (int i = tid; i < 128 * 32; i += 256) {
        float v = w5[i];
        s_w5[i] = pack2(v, v);
    }
    if (tid < 128) {
        float v0 = w6[tid], v1 = w6[128 + tid];
        s_w6[tid] = pack2(v0, v0);
        s_w6[128 + tid] = pack2(v1, v1);
        s_b5[tid] = b5[tid];
    }
    __syncthreads();

    const uint4* recA = (const uint4*)(in + ((size_t)b * 16384 + px0) * 32);
    const uint4* recB = (const uint4*)(in + ((size_t)b * 16384 + px0 + 256) * 32);
    u64 x2[32];
#pragma unroll
    for (int u = 0; u < 8; ++u) {
        uint4 A = recA[u], B = recB[u];
        x2[u * 4 + 0] = pack2(decpair(A.x), decpair(B.x));
        x2[u * 4 + 1] = pack2(decpair(A.y), decpair(B.y));
        x2[u * 4 + 2] = pack2(decpair(A.z), decpair(B.z));
        x2[u * 4 + 3] = pack2(decpair(A.w), decpair(B.w));
    }

    u64 acc0 = pack2(b6[0], b6[0]);
    u64 acc1 = pack2(b6[1], b6[1]);

    for (int j = 0; j < 128; ++j) {
        float bj = s_b5[j];
        u64 h = pack2(bj, bj);
        const ulonglong2* wr = reinterpret_cast<const ulonglong2*>(s_w5 + j * 32);
#pragma unroll
        for (int c2 = 0; c2 < 16; ++c2) {
            ulonglong2 wp = wr[c2];
            ffma2(h, x2[2 * c2], wp.x);
            ffma2(h, x2[2 * c2 + 1], wp.y);
        }
        float h0, h1;
        unpack2(h, h0, h1);
        u64 hr = pack2(fmaxf(h0, 0.0f), fmaxf(h1, 0.0f));
        ffma2(acc0, hr, s_w6[j]);
        ffma2(acc1, hr, s_w6[128 + j]);
    }

    float o00, o01, o10, o11;
    unpack2(acc0, o00, o01);
    unpack2(acc1, o10, o11);
    float* op = out + (size_t)b * 2 * HW_;
    op[px0] = o00;
    op[px0 + 256] = o01;
    op[HW_ + px0] = o10;
    op[HW_ + px0 + 256] = o11;
}

// ---------------------------------------------------------------------------
extern "C" void kernel_launch(void* const* d_in, const int* in_sizes, int n_in,
                              void* d_out, int out_size) {
    const float* x  = (const float*)d_in[0];
    const float* w0 = (const float*)d_in[2];
    const float* b0 = (const float*)d_in[3];
    const float* w1 = (const float*)d_in[4];
    const float* b1 = (const float*)d_in[5];
    const float* w2 = (const float*)d_in[6];
    const float* b2 = (const float*)d_in[7];
    const float* w3 = (const float*)d_in[8];
    const float* b3 = (const float*)d_in[9];
    const float* w4 = (const float*)d_in[10];
    const float* b4 = (const float*)d_in[11];
    const float* w5 = (const float*)d_in[12];
    const float* b5 = (const float*)d_in[13];
    const float* w6 = (const float*)d_in[14];
    const float* b6 = (const float*)d_in[15];

    uint32_t *bufA = nullptr, *bufB = nullptr;
    cudaGetSymbolAddress((void**)&bufA, g_bufA);
    cudaGetSymbolAddress((void**)&bufB, g_bufB);

    // smem sizes
    size_t smem0 = (size_t)(4 * 25 * 8 + 2 * 36 * 36 + 8) * 4;
    auto tsmem = [](int cin, int cout) {
        int A = 6 * 132 * cin * 4;
        int B_OFF = 1024 + ((A + 1023) & ~1023);
        int B = 25 * cout * cin * 4;
        int scratch = 256 * (cout + 4) * 4;
        return (size_t)(B_OFF + (B > scratch ? B : scratch));
    };

    cudaFuncSetAttribute(conv0, cudaFuncAttributeMaxDynamicSharedMemorySize, (int)smem0);
    cudaFuncSetAttribute(tconv<16, 16>, cudaFuncAttributeMaxDynamicSharedMemorySize,
                         (int)tsmem(16, 16));
    cudaFuncSetAttribute(tconv<16, 32>, cudaFuncAttributeMaxDynamicSharedMemorySize,
                         (int)tsmem(16, 32));
    cudaFuncSetAttribute(tconv<32, 32>, cudaFuncAttributeMaxDynamicSharedMemorySize,
                         (int)tsmem(32, 32));

    dim3 blk(256);
    conv0<<<dim3(16, 2, NB), blk, smem0>>>(x, w0, b0, bufA);
    tconv<16, 16><<<dim3(64, 1, NB), blk, tsmem(16, 16)>>>(bufA, w1, b1, bufB);
    tconv<16, 32><<<dim3(64, 1, NB), blk, tsmem(16, 32)>>>(bufB, w2, b2, bufA);
    tconv<32, 32><<<dim3(64, 1, NB), blk, tsmem(32, 32)>>>(bufA, w3, b3, bufB);
    tconv<32, 32><<<dim3(64, 1, NB), blk, tsmem(32, 32)>>>(bufB, w4, b4, bufA);
    conv56<<<dim3(HW_ / 512, NB), blk>>>(bufA, w5, b5, w6, b6, (float*)d_out);
}

// round 14
// speedup vs baseline: 1.8021x; 1.8021x over previous
#include <cuda_runtime.h>
#include <cstdint>

#define HW_ (128 * 128)
static constexpr int IMG = 128;
static constexpr int NB  = 304;
static constexpr size_t BUF_ELEMS = (size_t)NB * 32 * HW_;

// Activation records: CIN u32 per pixel; slot ci = bf16(xh) | bf16(xl)<<16
__device__ uint32_t g_bufA[BUF_ELEMS];
__device__ uint32_t g_bufB[BUF_ELEMS];

__constant__ int c_chidx[19][4] = {
    {1, 8, 19, 20}, {8, 9, 21, 22}, {9, 10, 23, 24}, {1, 11, 25, 26},
    {11, 12, 27, 28}, {12, 13, 29, 30}, {1, 2, 31, 32}, {2, 3, 33, 34},
    {3, 4, 35, 36}, {2, 16, 37, 38}, {1, 5, 39, 40}, {5, 6, 41, 42},
    {6, 7, 43, 44}, {5, 17, 45, 46}, {0, 1, 47, 48}, {0, 14, 49, 50},
    {0, 15, 51, 52}, {14, 16, 53, 54}, {15, 17, 55, 56}
};

typedef unsigned long long u64;

__device__ __forceinline__ u64 pack2(float lo, float hi) {
    u64 r; asm("mov.b64 %0, {%1, %2};" : "=l"(r) : "f"(lo), "f"(hi)); return r;
}
__device__ __forceinline__ void unpack2(u64 v, float& lo, float& hi) {
    asm("mov.b64 {%0, %1}, %2;" : "=f"(lo), "=f"(hi) : "l"(v));
}
__device__ __forceinline__ void ffma2(u64& d, u64 a, u64 b) {
    asm("fma.rn.f32x2 %0, %1, %2, %0;" : "+l"(d) : "l"(a), "l"(b));
}

// bf16 RNE split: v = hi_part + lo_part
__device__ __forceinline__ void bf16split(float v, uint32_t& hi, uint32_t& lo) {
    uint32_t ub = __float_as_uint(v);
    uint32_t hb = (ub + 0x7FFFu + ((ub >> 16) & 1u)) & 0xFFFF0000u;
    hi = hb >> 16;
    float lof = v - __uint_as_float(hb);
    uint32_t ul = __float_as_uint(lof);
    lo = (ul + 0x7FFFu + ((ul >> 16) & 1u)) >> 16;
}
__device__ __forceinline__ uint32_t packpair(float v) {
    uint32_t hi, lo; bf16split(v, hi, lo); return hi | (lo << 16);
}
__device__ __forceinline__ float decpair(uint32_t u) {
    return __uint_as_float(u << 16) + __uint_as_float(u & 0xFFFF0000u);
}

__device__ __forceinline__ void cpasync16(unsigned dst, const void* src, int sz) {
    asm volatile("cp.async.cg.shared.global [%0], [%1], 16, %2;"
                 :: "r"(dst), "l"(src), "r"(sz));
}
__device__ __forceinline__ void cpasync4(unsigned dst, const float* src, int sz) {
    asm volatile("cp.async.ca.shared.global [%0], [%1], 4, %2;"
                 :: "r"(dst), "l"(src), "r"(sz));
}
__device__ __forceinline__ void cpasync_commit() { asm volatile("cp.async.commit_group;"); }
__device__ __forceinline__ void cpasync_wait_all() {
    asm volatile("cp.async.wait_group 0;" ::: "memory");
}

#define SMEM_SWZ(off) ((off) ^ (((off) >> 3) & 0x70))

__device__ __forceinline__ uint32_t smem_u32(const void* p) {
    uint32_t a;
    asm("{ .reg .u64 t; cvta.to.shared.u64 t, %1; cvt.u32.u64 %0, t; }" : "=r"(a) : "l"(p));
    return a;
}
// ldmatrix x4 (baseline PTX, sm_75+)
__device__ __forceinline__ void ldsm4(uint32_t* r, uint32_t addr) {
    asm volatile("ldmatrix.sync.aligned.m8n8.x4.shared.b16 {%0,%1,%2,%3}, [%4];"
                 : "=r"(r[0]), "=r"(r[1]), "=r"(r[2]), "=r"(r[3]) : "r"(addr));
}
// mma.sync bf16 (baseline PTX, sm_80+) -> HMMA
__device__ __forceinline__ void mma_bf16(float* c, const uint32_t* a,
                                         uint32_t b0, uint32_t b1) {
    asm volatile(
        "mma.sync.aligned.m16n8k16.row.col.f32.bf16.bf16.f32 "
        "{%0,%1,%2,%3}, {%4,%5,%6,%7}, {%8,%9}, {%0,%1,%2,%3};"
        : "+f"(c[0]), "+f"(c[1]), "+f"(c[2]), "+f"(c[3])
        : "r"(a[0]), "r"(a[1]), "r"(a[2]), "r"(a[3]), "r"(b0), "r"(b1));
}

// One shared declaration for every dynamic-smem kernel in this TU.
extern __shared__ __align__(1024) unsigned char dynsmem[];

// ---------------------------------------------------------------------------
// HMMA 5x5 conv + relu.  Grid (32 row-quads, 1, NB), 512 thr (16 warps).
// CTA: 4 output rows x 128 px (M=512) x COUT.  Warp: 32 px (2 m16 frags).
// A: 8 input rows x 132 px of CIN-u32 records, swizzled; ldmatrix direct from
// the shifted window.  B: [tap][pass][co][2*CIN bf16] with BOTH passes
// resident (pass0 (wh,wh) = x*wh; pass1 (wl,0) = xh*wl) so A fragments are
// shared between passes.  B tap-chunked for CIN=32 (11 taps/chunk).
// f32 accumulators in registers.
// ---------------------------------------------------------------------------
template <int CIN, int COUT, int CHUNK>
__global__ __launch_bounds__(512, 1)
void tconv(const uint32_t* __restrict__ in_rec, const float* __restrict__ w,
           const float* __restrict__ bias, uint32_t* __restrict__ out_rec) {
    constexpr int RECB = CIN * 4;                 // bytes per input record
    constexpr int KB   = CIN * 4;                 // bytes per co per (tap,pass)
    constexpr int KS   = CIN / 8;                 // K-steps of 16 bf16
    constexpr int NG   = COUT / 8;                // 8-wide n-groups
    constexpr int A_OFF = 1024;
    constexpr int A_BYTES = 8 * 132 * RECB;       // multiple of 1024
    constexpr int B_OFF = A_OFF + A_BYTES;
    constexpr int U = RECB / 16;                  // 16B units per record

    unsigned char* smem = dynsmem;
    const uint32_t sb = smem_u32(smem);
    const int tid  = threadIdx.x;
    const int wnum = tid >> 5;
    const int lane = tid & 31;
    const int y0   = blockIdx.x * 4;
    const int b    = blockIdx.z;
    const size_t img = (size_t)b * 16384;

    if (tid < COUT) ((float*)smem)[tid] = bias[tid];

    // ---- stage A: rows y0-2..y0+5, 132 px, zfill halo ----
    {
        constexpr int TOT = 8 * 132 * U;
        for (int idx = tid; idx < TOT; idx += 512) {
            int pix = idx / U, u = idx - pix * U;
            int row = pix / 132, xc = pix - row * 132;
            int y = y0 - 2 + row, x = xc - 2;
            bool v = ((unsigned)y < 128u) & ((unsigned)x < 128u);
            const char* src =
                (const char*)(in_rec + (img + (v ? (size_t)(y * 128 + x) : 0)) * CIN) + u * 16;
            unsigned rel = (unsigned)(pix * RECB + u * 16);
            cpasync16(sb + A_OFF + SMEM_SWZ(rel), src, v ? 16 : 0);
        }
        cpasync_commit();
    }

    // per-thread ldmatrix address components (validated in R13)
    const int a_px = ((lane >> 3) & 1) * 8 + (lane & 7);
    const int a_kb = (lane >> 4) * 16;
    const int b_n  = ((lane >> 4) & 1) * 8 + (lane & 7);
    const int b_kb = ((lane >> 3) & 1) * 16;
    const int wrow = wnum >> 2;           // output row within quad (0..3)
    const int wcol = (wnum & 3) * 32;     // x-base of this warp's 32 px

    float acc[2][NG][4];
#pragma unroll
    for (int f = 0; f < 2; ++f)
#pragma unroll
        for (int g = 0; g < NG; ++g)
#pragma unroll
            for (int i = 0; i < 4; ++i) acc[f][g][i] = 0.0f;

    const uint32_t sbA = sb + A_OFF;
    const uint32_t sbB = sb + B_OFF;

    bool firstA = true;
#pragma unroll 1
    for (int t0 = 0; t0 < 25; t0 += CHUNK) {
        const int nt = (25 - t0 < CHUNK) ? (25 - t0) : CHUNK;
        if (t0) __syncthreads();          // previous chunk's compute done with B

        // stage B chunk: both passes, computed bf16 split from fp32 weights
        {
            const int tot = nt * COUT * CIN;
            for (int i = tid; i < tot; i += 512) {
                int ci = i % CIN;
                int co = (i / CIN) % COUT;
                int tl = i / (CIN * COUT);
                float wv = w[((size_t)co * CIN + ci) * 25 + t0 + tl];
                uint32_t hi, lo;
                bf16split(wv, hi, lo);
                *(uint32_t*)(smem + B_OFF +
                    SMEM_SWZ((unsigned)(((tl * 2 + 0) * COUT + co) * KB + ci * 4))) =
                    hi | (hi << 16);
                *(uint32_t*)(smem + B_OFF +
                    SMEM_SWZ((unsigned)(((tl * 2 + 1) * COUT + co) * KB + ci * 4))) = lo;
            }
        }
        if (firstA) { cpasync_wait_all(); firstA = false; }
        __syncthreads();

#pragma unroll 1
        for (int tl = 0; tl < nt; ++tl) {
            const int tap = t0 + tl;
            const int dy = tap / 5, dx = tap - dy * 5;
            unsigned abase =
                (unsigned)(((wrow + dy) * 132 + wcol + dx + a_px) * RECB + a_kb);
            unsigned bb0 = (unsigned)(((tl * 2 + 0) * COUT + b_n) * KB + b_kb);
            unsigned bb1 = (unsigned)(((tl * 2 + 1) * COUT + b_n) * KB + b_kb);
#pragma unroll
            for (int kc = 0; kc < KS; ++kc) {
                uint32_t a0[4], a1[4];
                ldsm4(a0, sbA + SMEM_SWZ(abase + kc * 32));
                ldsm4(a1, sbA + SMEM_SWZ(abase + 16 * RECB + kc * 32));
                uint32_t bf0[NG / 2][4], bf1[NG / 2][4];
#pragma unroll
                for (int gp = 0; gp < NG / 2; ++gp) {
                    ldsm4(bf0[gp], sbB + SMEM_SWZ(bb0 + gp * 16 * KB + kc * 32));
                    ldsm4(bf1[gp], sbB + SMEM_SWZ(bb1 + gp * 16 * KB + kc * 32));
                }
#pragma unroll
                for (int g = 0; g < NG; ++g) {
                    uint32_t p00 = bf0[g >> 1][(g & 1) * 2];
                    uint32_t p01 = bf0[g >> 1][(g & 1) * 2 + 1];
                    mma_bf16(acc[0][g], a0, p00, p01);
                    mma_bf16(acc[1][g], a1, p00, p01);
                    uint32_t p10 = bf1[g >> 1][(g & 1) * 2];
                    uint32_t p11 = bf1[g >> 1][(g & 1) * 2 + 1];
                    mma_bf16(acc[0][g], a0, p10, p11);
                    mma_bf16(acc[1][g], a1, p10, p11);
                }
            }
        }
    }

    __syncthreads();                      // before reusing B region as scratch

    // ---- epilogue: +bias, relu, pack pairs, smem transpose, coalesced out ----
    {
        const float* sbias = (const float*)smem;
        uint32_t* so = (uint32_t*)(smem + B_OFF);
        constexpr int STR = COUT + 4;     // u32 stride, keeps 16B px alignment
#pragma unroll
        for (int f = 0; f < 2; ++f) {
            int px = wrow * 128 + wcol + f * 16 + (lane >> 2);
#pragma unroll
            for (int g = 0; g < NG; ++g) {
                int co = g * 8 + (lane & 3) * 2;
                float v0 = fmaxf(acc[f][g][0] + sbias[co], 0.0f);
                float v1 = fmaxf(acc[f][g][1] + sbias[co + 1], 0.0f);
                float v2 = fmaxf(acc[f][g][2] + sbias[co], 0.0f);
                float v3 = fmaxf(acc[f][g][3] + sbias[co + 1], 0.0f);
                so[px * STR + co]           = packpair(v0);
                so[px * STR + co + 1]       = packpair(v1);
                so[(px + 8) * STR + co]     = packpair(v2);
                so[(px + 8) * STR + co + 1] = packpair(v3);
            }
        }
        __syncthreads();

        constexpr int CH = COUT / 4;      // uint4 chunks per pixel
        const int u  = tid & (CH - 1);
        const int pb = tid / CH;
#pragma unroll
        for (int p = pb; p < 512; p += 512 / CH) {
            uint4 val;
            val.x = so[p * STR + u * 4 + 0];
            val.y = so[p * STR + u * 4 + 1];
            val.z = so[p * STR + u * 4 + 2];
            val.w = so[p * STR + u * 4 + 3];
            int y = y0 + (p >> 7), x = p & 127;
            *(uint4*)(out_rec + (img + (size_t)y * 128 + x) * COUT + u * 4) = val;
        }
    }
}

// ---------------------------------------------------------------------------
// Layer 0: FFMA2 5x5 conv with gather (4 -> 16), writes 16-u32 records.
// ---------------------------------------------------------------------------
__global__ __launch_bounds__(256, 3) void conv0(const float* __restrict__ in,
                                                const float* __restrict__ w,
                                                const float* __restrict__ bias,
                                                uint32_t* __restrict__ out) {
    constexpr int CIN = 4, CO = 8;
    constexpr int SW_SZ = CIN * 25 * CO;
    constexpr int TILE  = 36 * 36;
    float* smem = (float*)dynsmem;
    float* s_w  = smem;
    float* s_in = smem + SW_SZ;
    float* s_b  = s_in + 2 * TILE;

    const int tid = threadIdx.x;
    const int tile = blockIdx.x, g = blockIdx.y, b = blockIdx.z;
    const int tile_x = (tile & 3) * 32, tile_y = (tile >> 2) * 32;

    for (int idx = tid; idx < SW_SZ; idx += 256) {
        int co = idx & 7, r = idx >> 3;
        int ci = r / 25, tap = r % 25;
        s_w[idx] = w[((size_t)(g * CO + co) * CIN + ci) * 25 + tap];
    }
    if (tid < CO) s_b[tid] = bias[g * CO + tid];

    int n = b / 19, e = b - n * 19;
    const float* src = in + (size_t)n * 57 * HW_;

    int off[6], szb[6];
#pragma unroll
    for (int k = 0; k < 6; ++k) {
        int idx = tid + k * 256;
        int r = idx / 36, c = idx - r * 36;
        int ih = tile_y + r - 2, iw = tile_x + c - 2;
        bool v = ((unsigned)ih < 128u) && ((unsigned)iw < 128u);
        szb[k] = v ? 4 : 0;
        off[k] = v ? (ih * IMG + iw) : 0;
    }

    const unsigned s_in_b = (unsigned)__cvta_generic_to_shared(s_in);
    const int tx = tid & 31, ty = tid >> 5;

    u64 acc[4][4];
#pragma unroll
    for (int p = 0; p < 4; ++p)
#pragma unroll
        for (int c = 0; c < 4; ++c) acc[p][c] = 0ull;

    auto stage = [&](int ci_n, int bi) {
        const float* sp = src + (size_t)c_chidx[e][ci_n] * HW_;
        unsigned base = s_in_b + (unsigned)(bi * TILE * 4);
#pragma unroll
        for (int k = 0; k < 6; ++k) {
            int idx = tid + k * 256;
            if (k < 5 || tid < (TILE - 5 * 256))
                cpasync4(base + (unsigned)idx * 4u, sp + off[k], szb[k]);
        }
        cpasync_commit();
    };

    stage(0, 0);
    cpasync_wait_all();
    __syncthreads();

    for (int ci = 0; ci < CIN; ++ci) {
        if (ci + 1 < CIN) stage(ci + 1, (ci + 1) & 1);
        const float* cb = s_in + (ci & 1) * TILE;
        const float* wbase = s_w + ci * 25 * CO;
#pragma unroll
        for (int dx = 0; dx < 5; ++dx) {
            u64 dup[8];
#pragma unroll
            for (int j = 0; j < 8; ++j) {
                float v = cb[(ty * 4 + j) * 36 + tx + dx];
                dup[j] = pack2(v, v);
            }
#pragma unroll
            for (int dy = 0; dy < 5; ++dy) {
                const ulonglong2* wr =
                    reinterpret_cast<const ulonglong2*>(wbase + (dy * 5 + dx) * CO);
                ulonglong2 wp0 = wr[0], wp1 = wr[1];
#pragma unroll
                for (int p = 0; p < 4; ++p) {
                    ffma2(acc[p][0], dup[dy + p], wp0.x);
                    ffma2(acc[p][1], dup[dy + p], wp0.y);
                    ffma2(acc[p][2], dup[dy + p], wp1.x);
                    ffma2(acc[p][3], dup[dy + p], wp1.y);
                }
            }
        }
        if (ci + 1 < CIN) {
            cpasync_wait_all();
            __syncthreads();
        }
    }

    // epilogue -> 16-u32 records (slot = g*8 + co)
    const int y0 = tile_y + ty * 4, x = tile_x + tx;
    uint32_t* ob = out + (size_t)b * 16384 * 16 + g * CO;
#pragma unroll
    for (int p = 0; p < 4; ++p) {
        uint32_t* op = ob + (size_t)((y0 + p) * 128 + x) * 16;
#pragma unroll
        for (int c = 0; c < 4; ++c) {
            float v0, v1;
            unpack2(acc[p][c], v0, v1);
            v0 = fmaxf(v0 + s_b[2 * c], 0.0f);
            v1 = fmaxf(v1 + s_b[2 * c + 1], 0.0f);
            op[2 * c]     = packpair(v0);
            op[2 * c + 1] = packpair(v1);
        }
    }
}

// ---------------------------------------------------------------------------
// fused 1x1: 32 -> 128 (relu) -> 2, reads 32-u32 records, writes fp32 output.
// ---------------------------------------------------------------------------
__global__ __launch_bounds__(256) void conv56(const uint32_t* __restrict__ in,
                                              const float* __restrict__ w5,
                                              const float* __restrict__ b5,
                                              const float* __restrict__ w6,
                                              const float* __restrict__ b6,
                                              float* __restrict__ out) {
    __shared__ __align__(16) u64 s_w5[128 * 32];
    __shared__ __align__(16) u64 s_w6[2 * 128];
    __shared__ float s_b5[128];

    const int tid = threadIdx.x;
    const int b   = blockIdx.y;
    const int px0 = blockIdx.x * 512 + tid;

    for (int i = tid; i < 128 * 32; i += 256) {
        float v = w5[i];
        s_w5[i] = pack2(v, v);
    }
    if (tid < 128) {
        float v0 = w6[tid], v1 = w6[128 + tid];
        s_w6[tid] = pack2(v0, v0);
        s_w6[128 + tid] = pack2(v1, v1);
        s_b5[tid] = b5[tid];
    }
    __syncthreads();

    const uint4* recA = (const uint4*)(in + ((size_t)b * 16384 + px0) * 32);
    const uint4* recB = (const uint4*)(in + ((size_t)b * 16384 + px0 + 256) * 32);
    u64 x2[32];
#pragma unroll
    for (int u = 0; u < 8; ++u) {
        uint4 A = recA[u], B = recB[u];
        x2[u * 4 + 0] = pack2(decpair(A.x), decpair(B.x));
        x2[u * 4 + 1] = pack2(decpair(A.y), decpair(B.y));
        x2[u * 4 + 2] = pack2(decpair(A.z), decpair(B.z));
        x2[u * 4 + 3] = pack2(decpair(A.w), decpair(B.w));
    }

    u64 acc0 = pack2(b6[0], b6[0]);
    u64 acc1 = pack2(b6[1], b6[1]);

    for (int j = 0; j < 128; ++j) {
        float bj = s_b5[j];
        u64 h = pack2(bj, bj);
        const ulonglong2* wr = reinterpret_cast<const ulonglong2*>(s_w5 + j * 32);
#pragma unroll
        for (int c2 = 0; c2 < 16; ++c2) {
            ulonglong2 wp = wr[c2];
            ffma2(h, x2[2 * c2], wp.x);
            ffma2(h, x2[2 * c2 + 1], wp.y);
        }
        float h0, h1;
        unpack2(h, h0, h1);
        u64 hr = pack2(fmaxf(h0, 0.0f), fmaxf(h1, 0.0f));
        ffma2(acc0, hr, s_w6[j]);
        ffma2(acc1, hr, s_w6[128 + j]);
    }

    float o00, o01, o10, o11;
    unpack2(acc0, o00, o01);
    unpack2(acc1, o10, o11);
    float* op = out + (size_t)b * 2 * HW_;
    op[px0] = o00;
    op[px0 + 256] = o01;
    op[HW_ + px0] = o10;
    op[HW_ + px0 + 256] = o11;
}

// ---------------------------------------------------------------------------
extern "C" void kernel_launch(void* const* d_in, const int* in_sizes, int n_in,
                              void* d_out, int out_size) {
    const float* x  = (const float*)d_in[0];
    const float* w0 = (const float*)d_in[2];
    const float* b0 = (const float*)d_in[3];
    const float* w1 = (const float*)d_in[4];
    const float* b1 = (const float*)d_in[5];
    const float* w2 = (const float*)d_in[6];
    const float* b2 = (const float*)d_in[7];
    const float* w3 = (const float*)d_in[8];
    const float* b3 = (const float*)d_in[9];
    const float* w4 = (const float*)d_in[10];
    const float* b4 = (const float*)d_in[11];
    const float* w5 = (const float*)d_in[12];
    const float* b5 = (const float*)d_in[13];
    const float* w6 = (const float*)d_in[14];
    const float* b6 = (const float*)d_in[15];

    uint32_t *bufA = nullptr, *bufB = nullptr;
    cudaGetSymbolAddress((void**)&bufA, g_bufA);
    cudaGetSymbolAddress((void**)&bufB, g_bufB);

    size_t smem0 = (size_t)(4 * 25 * 8 + 2 * 36 * 36 + 8) * 4;
    auto tsmem = [](int cin, int cout, int chunk) {
        int A = 8 * 132 * cin * 4;
        int Bb = chunk * 2 * cout * cin * 4;
        int scratch = 512 * (cout + 4) * 4;
        int bsz = Bb > scratch ? Bb : scratch;
        return (size_t)(1024 + A + bsz);
    };

    cudaFuncSetAttribute(conv0, cudaFuncAttributeMaxDynamicSharedMemorySize, (int)smem0);
    cudaFuncSetAttribute(tconv<16, 16, 25>, cudaFuncAttributeMaxDynamicSharedMemorySize,
                         (int)tsmem(16, 16, 25));
    cudaFuncSetAttribute(tconv<16, 32, 25>, cudaFuncAttributeMaxDynamicSharedMemorySize,
                         (int)tsmem(16, 32, 25));
    cudaFuncSetAttribute(tconv<32, 32, 11>, cudaFuncAttributeMaxDynamicSharedMemorySize,
                         (int)tsmem(32, 32, 11));

    dim3 blk2(256), blk5(512);
    conv0<<<dim3(16, 2, NB), blk2, smem0>>>(x, w0, b0, bufA);
    tconv<16, 16, 25><<<dim3(32, 1, NB), blk5, tsmem(16, 16, 25)>>>(bufA, w1, b1, bufB);
    tconv<16, 32, 25><<<dim3(32, 1, NB), blk5, tsmem(16, 32, 25)>>>(bufB, w2, b2, bufA);
    tconv<32, 32, 11><<<dim3(32, 1, NB), blk5, tsmem(32, 32, 11)>>>(bufA, w3, b3, bufB);
    tconv<32, 32, 11><<<dim3(32, 1, NB), blk5, tsmem(32, 32, 11)>>>(bufB, w4, b4, bufA);
    conv56<<<dim3(HW_ / 512, NB), blk2>>>(bufA, w5, b5, w6, b6, (float*)d_out);
}

// round 15
// speedup vs baseline: 2.0245x; 1.1234x over previous
#include <cuda_runtime.h>
#include <cstdint>

#define HW_ (128 * 128)
static constexpr int IMG = 128;
static constexpr int NB  = 304;
static constexpr size_t BUF_ELEMS = (size_t)NB * 32 * HW_;

// Activation records, C channels/pixel, C u32 per pixel:
//   u32 slots [0..C/2)  = bf16 hi pairs  (h[2c] | h[2c+1]<<16)
//   u32 slots [C/2..C)  = bf16 lo pairs  (l[2c] | l[2c+1]<<16)
// As a bf16[2C] K-vector: k in [0,C) = xh[k], k in [C,2C) = xl[k-C].
__device__ uint32_t g_bufA[BUF_ELEMS];
__device__ uint32_t g_bufB[BUF_ELEMS];

__constant__ int c_chidx[19][4] = {
    {1, 8, 19, 20}, {8, 9, 21, 22}, {9, 10, 23, 24}, {1, 11, 25, 26},
    {11, 12, 27, 28}, {12, 13, 29, 30}, {1, 2, 31, 32}, {2, 3, 33, 34},
    {3, 4, 35, 36}, {2, 16, 37, 38}, {1, 5, 39, 40}, {5, 6, 41, 42},
    {6, 7, 43, 44}, {5, 17, 45, 46}, {0, 1, 47, 48}, {0, 14, 49, 50},
    {0, 15, 51, 52}, {14, 16, 53, 54}, {15, 17, 55, 56}
};

typedef unsigned long long u64;

__device__ __forceinline__ u64 pack2(float lo, float hi) {
    u64 r; asm("mov.b64 %0, {%1, %2};" : "=l"(r) : "f"(lo), "f"(hi)); return r;
}
__device__ __forceinline__ void unpack2(u64 v, float& lo, float& hi) {
    asm("mov.b64 {%0, %1}, %2;" : "=f"(lo), "=f"(hi) : "l"(v));
}
__device__ __forceinline__ void ffma2(u64& d, u64 a, u64 b) {
    asm("fma.rn.f32x2 %0, %1, %2, %0;" : "+l"(d) : "l"(a), "l"(b));
}

// bf16 RNE split: v = hi_part + lo_part
__device__ __forceinline__ void bf16split(float v, uint32_t& hi, uint32_t& lo) {
    uint32_t ub = __float_as_uint(v);
    uint32_t hb = (ub + 0x7FFFu + ((ub >> 16) & 1u)) & 0xFFFF0000u;
    hi = hb >> 16;
    float lof = v - __uint_as_float(hb);
    uint32_t ul = __float_as_uint(lof);
    lo = (ul + 0x7FFFu + ((ul >> 16) & 1u)) >> 16;
}
__device__ __forceinline__ float blo16(uint32_t u) { return __uint_as_float(u << 16); }
__device__ __forceinline__ float bhi16(uint32_t u) {
    return __uint_as_float(u & 0xFFFF0000u);
}

__device__ __forceinline__ void cpasync16(unsigned dst, const void* src, int sz) {
    asm volatile("cp.async.cg.shared.global [%0], [%1], 16, %2;"
                 :: "r"(dst), "l"(src), "r"(sz));
}
__device__ __forceinline__ void cpasync4(unsigned dst, const float* src, int sz) {
    asm volatile("cp.async.ca.shared.global [%0], [%1], 4, %2;"
                 :: "r"(dst), "l"(src), "r"(sz));
}
__device__ __forceinline__ void cpasync_commit() { asm volatile("cp.async.commit_group;"); }
__device__ __forceinline__ void cpasync_wait_all() {
    asm volatile("cp.async.wait_group 0;" ::: "memory");
}

#define SMEM_SWZ(off) ((off) ^ (((off) >> 3) & 0x70))

__device__ __forceinline__ uint32_t smem_u32(const void* p) {
    uint32_t a;
    asm("{ .reg .u64 t; cvta.to.shared.u64 t, %1; cvt.u32.u64 %0, t; }" : "=r"(a) : "l"(p));
    return a;
}
// ldmatrix x4 (baseline PTX, sm_75+)
__device__ __forceinline__ void ldsm4(uint32_t* r, uint32_t addr) {
    asm volatile("ldmatrix.sync.aligned.m8n8.x4.shared.b16 {%0,%1,%2,%3}, [%4];"
                 : "=r"(r[0]), "=r"(r[1]), "=r"(r[2]), "=r"(r[3]) : "r"(addr));
}
// mma.sync bf16 (baseline PTX, sm_80+) -> HMMA
__device__ __forceinline__ void mma_bf16(float* c, const uint32_t* a,
                                         uint32_t b0, uint32_t b1) {
    asm volatile(
        "mma.sync.aligned.m16n8k16.row.col.f32.bf16.bf16.f32 "
        "{%0,%1,%2,%3}, {%4,%5,%6,%7}, {%8,%9}, {%0,%1,%2,%3};"
        : "+f"(c[0]), "+f"(c[1]), "+f"(c[2]), "+f"(c[3])
        : "r"(a[0]), "r"(a[1]), "r"(a[2]), "r"(a[3]), "r"(b0), "r"(b1));
}

// One shared declaration for every dynamic-smem kernel in this TU.
extern __shared__ __align__(1024) unsigned char dynsmem[];

// ---------------------------------------------------------------------------
// HMMA 5x5 conv + relu.  Grid (32 row-quads, 1, NB), 512 thr (16 warps).
// CTA: 4 output rows x 128 px (M=512) x COUT.  Warp: 32 px (2 m16 frags).
// Split-record scheme: main pass xh*wh over K=CIN; corr pass (xh*wl + xl*wh)
// over K=2*CIN with B = [wl | wh].  3*CIN total K-work (25% less than the
// naive 2-pass).  A fragments are loaded ONCE per kc and feed both passes.
// B per tap: [main COUT x 2*CIN bytes][corr COUT x 4*CIN bytes], tap-chunked.
// ---------------------------------------------------------------------------
template <int CIN, int COUT, int CHUNK>
__global__ __launch_bounds__(512, 1)
void tconv(const uint32_t* __restrict__ in_rec, const float* __restrict__ w,
           const float* __restrict__ bias, uint32_t* __restrict__ out_rec) {
    constexpr int RECB = CIN * 4;                 // bytes per input record
    constexpr int KBM  = CIN * 2;                 // main B row bytes (K=CIN)
    constexpr int KBC  = CIN * 4;                 // corr B row bytes (K=2CIN)
    constexpr int KS2  = CIN / 8;                 // corr K-steps
    constexpr int KSM  = CIN / 16;                // main K-steps
    constexpr int NG   = COUT / 8;                // 8-wide n-groups
    constexpr int MAINB = COUT * KBM;             // main block bytes (512B mult.)
    constexpr int TAPB  = 3 * MAINB;              // per-tap block bytes
    constexpr int A_OFF = 1024;
    constexpr int A_BYTES = 8 * 132 * RECB;       // multiple of 1024
    constexpr int B_OFF = A_OFF + A_BYTES;
    constexpr int U = RECB / 16;                  // 16B units per record

    unsigned char* smem = dynsmem;
    const uint32_t sb = smem_u32(smem);
    const int tid  = threadIdx.x;
    const int wnum = tid >> 5;
    const int lane = tid & 31;
    const int y0   = blockIdx.x * 4;
    const int b    = blockIdx.z;
    const size_t img = (size_t)b * 16384;

    if (tid < COUT) ((float*)smem)[tid] = bias[tid];

    // ---- stage A: rows y0-2..y0+5, 132 px, zfill halo ----
    {
        constexpr int TOT = 8 * 132 * U;
        for (int idx = tid; idx < TOT; idx += 512) {
            int pix = idx / U, u = idx - pix * U;
            int row = pix / 132, xc = pix - row * 132;
            int y = y0 - 2 + row, x = xc - 2;
            bool v = ((unsigned)y < 128u) & ((unsigned)x < 128u);
            const char* src =
                (const char*)(in_rec + (img + (v ? (size_t)(y * 128 + x) : 0)) * CIN) + u * 16;
            unsigned rel = (unsigned)(pix * RECB + u * 16);
            cpasync16(sb + A_OFF + SMEM_SWZ(rel), src, v ? 16 : 0);
        }
        cpasync_commit();
    }

    // per-thread ldmatrix address components (validated R13/R14)
    const int a_px = ((lane >> 3) & 1) * 8 + (lane & 7);
    const int a_kb = (lane >> 4) * 16;
    const int b_n  = ((lane >> 4) & 1) * 8 + (lane & 7);
    const int b_kb = ((lane >> 3) & 1) * 16;
    const int wrow = wnum >> 2;           // output row within quad (0..3)
    const int wcol = (wnum & 3) * 32;     // x-base of this warp's 32 px

    float acc[2][NG][4];
#pragma unroll
    for (int f = 0; f < 2; ++f)
#pragma unroll
        for (int g = 0; g < NG; ++g)
#pragma unroll
            for (int i = 0; i < 4; ++i) acc[f][g][i] = 0.0f;

    const uint32_t sbA = sb + A_OFF;
    const uint32_t sbB = sb + B_OFF;

    bool firstA = true;
#pragma unroll 1
    for (int t0 = 0; t0 < 25; t0 += CHUNK) {
        const int nt = (25 - t0 < CHUNK) ? (25 - t0) : CHUNK;
        if (t0) __syncthreads();          // previous chunk's compute done with B

        // stage B chunk: main (wh pairs) + corr ([wl | wh])
        {
            const int tot = nt * COUT * (CIN / 2);
            for (int i = tid; i < tot; i += 512) {
                int c  = i % (CIN / 2);                 // u32 pair index
                int co = (i / (CIN / 2)) % COUT;
                int tl = i / ((CIN / 2) * COUT);
                int tap = t0 + tl;
                float wv0 = w[((size_t)co * CIN + 2 * c) * 25 + tap];
                float wv1 = w[((size_t)co * CIN + 2 * c + 1) * 25 + tap];
                uint32_t h0, l0, h1, l1;
                bf16split(wv0, h0, l0);
                bf16split(wv1, h1, l1);
                uint32_t hp = h0 | (h1 << 16);
                uint32_t lp = l0 | (l1 << 16);
                unsigned tb = (unsigned)(tl * TAPB);
                // main: row co, slot c
                *(uint32_t*)(smem + B_OFF +
                    SMEM_SWZ(tb + (unsigned)(co * KBM + c * 4))) = hp;
                // corr: row co; k<CIN -> wl pairs; k>=CIN -> wh pairs
                unsigned cb = tb + (unsigned)MAINB + (unsigned)(co * KBC);
                *(uint32_t*)(smem + B_OFF + SMEM_SWZ(cb + (unsigned)(c * 4))) = lp;
                *(uint32_t*)(smem + B_OFF +
                    SMEM_SWZ(cb + (unsigned)((CIN / 2 + c) * 4))) = hp;
            }
        }
        if (firstA) { cpasync_wait_all(); firstA = false; }
        __syncthreads();

#pragma unroll 1
        for (int tl = 0; tl < nt; ++tl) {
            const int tap = t0 + tl;
            const int dy = tap / 5, dx = tap - dy * 5;
            unsigned abase =
                (unsigned)(((wrow + dy) * 132 + wcol + dx + a_px) * RECB + a_kb);
            unsigned mainB = (unsigned)(tl * TAPB) + (unsigned)(b_n * KBM) + b_kb;
            unsigned corrB = (unsigned)(tl * TAPB + MAINB) +
                             (unsigned)(b_n * KBC) + b_kb;
#pragma unroll
            for (int kc = 0; kc < KS2; ++kc) {
                uint32_t a0[4], a1[4];
                ldsm4(a0, sbA + SMEM_SWZ(abase + kc * 32));
                ldsm4(a1, sbA + SMEM_SWZ(abase + 16 * RECB + kc * 32));
                // corr pass: B = [wl | wh], K=2*CIN
                uint32_t bc[NG / 2][4];
#pragma unroll
                for (int gp = 0; gp < NG / 2; ++gp)
                    ldsm4(bc[gp], sbB + SMEM_SWZ(corrB + gp * 16 * KBC + kc * 32));
#pragma unroll
                for (int g = 0; g < NG; ++g) {
                    uint32_t p0 = bc[g >> 1][(g & 1) * 2];
                    uint32_t p1 = bc[g >> 1][(g & 1) * 2 + 1];
                    mma_bf16(acc[0][g], a0, p0, p1);
                    mma_bf16(acc[1][g], a1, p0, p1);
                }
                // main pass: B = wh, K=CIN (first KSM k-steps share A frags)
                if (kc < KSM) {
                    uint32_t bm[NG / 2][4];
#pragma unroll
                    for (int gp = 0; gp < NG / 2; ++gp)
                        ldsm4(bm[gp], sbB + SMEM_SWZ(mainB + gp * 16 * KBM + kc * 32));
#pragma unroll
                    for (int g = 0; g < NG; ++g) {
                        uint32_t p0 = bm[g >> 1][(g & 1) * 2];
                        uint32_t p1 = bm[g >> 1][(g & 1) * 2 + 1];
                        mma_bf16(acc[0][g], a0, p0, p1);
                        mma_bf16(acc[1][g], a1, p0, p1);
                    }
                }
            }
        }
    }

    __syncthreads();                      // before reusing B region as scratch

    // ---- epilogue: +bias, relu, split-pack, smem transpose, coalesced out ----
    {
        const float* sbias = (const float*)smem;
        uint32_t* so = (uint32_t*)(smem + B_OFF);
        constexpr int STR = COUT + 4;     // u32 stride, keeps 16B px alignment
#pragma unroll
        for (int f = 0; f < 2; ++f) {
            int px = wrow * 128 + wcol + f * 16 + (lane >> 2);
#pragma unroll
            for (int g = 0; g < NG; ++g) {
                int co = g * 8 + (lane & 3) * 2;      // channel pair (co, co+1)
                float v0 = fmaxf(acc[f][g][0] + sbias[co], 0.0f);
                float v1 = fmaxf(acc[f][g][1] + sbias[co + 1], 0.0f);
                float v2 = fmaxf(acc[f][g][2] + sbias[co], 0.0f);
                float v3 = fmaxf(acc[f][g][3] + sbias[co + 1], 0.0f);
                uint32_t h0, l0, h1, l1;
                bf16split(v0, h0, l0);
                bf16split(v1, h1, l1);
                so[px * STR + (co >> 1)]            = h0 | (h1 << 16);
                so[px * STR + COUT / 2 + (co >> 1)] = l0 | (l1 << 16);
                bf16split(v2, h0, l0);
                bf16split(v3, h1, l1);
                so[(px + 8) * STR + (co >> 1)]            = h0 | (h1 << 16);
                so[(px + 8) * STR + COUT / 2 + (co >> 1)] = l0 | (l1 << 16);
            }
        }
        __syncthreads();

        constexpr int CH = COUT / 4;      // uint4 chunks per pixel
        const int u  = tid & (CH - 1);
        const int pb = tid / CH;
#pragma unroll
        for (int p = pb; p < 512; p += 512 / CH) {
            uint4 val;
            val.x = so[p * STR + u * 4 + 0];
            val.y = so[p * STR + u * 4 + 1];
            val.z = so[p * STR + u * 4 + 2];
            val.w = so[p * STR + u * 4 + 3];
            int y = y0 + (p >> 7), x = p & 127;
            *(uint4*)(out_rec + (img + (size_t)y * 128 + x) * COUT + u * 4) = val;
        }
    }
}

// ---------------------------------------------------------------------------
// Layer 0: FFMA2 5x5 conv with gather (4 -> 16), writes split records.
// ---------------------------------------------------------------------------
__global__ __launch_bounds__(256, 3) void conv0(const float* __restrict__ in,
                                                const float* __restrict__ w,
                                                const float* __restrict__ bias,
                                                uint32_t* __restrict__ out) {
    constexpr int CIN = 4, CO = 8;
    constexpr int SW_SZ = CIN * 25 * CO;
    constexpr int TILE  = 36 * 36;
    float* smem = (float*)dynsmem;
    float* s_w  = smem;
    float* s_in = smem + SW_SZ;
    float* s_b  = s_in + 2 * TILE;

    const int tid = threadIdx.x;
    const int tile = blockIdx.x, g = blockIdx.y, b = blockIdx.z;
    const int tile_x = (tile & 3) * 32, tile_y = (tile >> 2) * 32;

    for (int idx = tid; idx < SW_SZ; idx += 256) {
        int co = idx & 7, r = idx >> 3;
        int ci = r / 25, tap = r % 25;
        s_w[idx] = w[((size_t)(g * CO + co) * CIN + ci) * 25 + tap];
    }
    if (tid < CO) s_b[tid] = bias[g * CO + tid];

    int n = b / 19, e = b - n * 19;
    const float* src = in + (size_t)n * 57 * HW_;

    int off[6], szb[6];
#pragma unroll
    for (int k = 0; k < 6; ++k) {
        int idx = tid + k * 256;
        int r = idx / 36, c = idx - r * 36;
        int ih = tile_y + r - 2, iw = tile_x + c - 2;
        bool v = ((unsigned)ih < 128u) && ((unsigned)iw < 128u);
        szb[k] = v ? 4 : 0;
        off[k] = v ? (ih * IMG + iw) : 0;
    }

    const unsigned s_in_b = (unsigned)__cvta_generic_to_shared(s_in);
    const int tx = tid & 31, ty = tid >> 5;

    u64 acc[4][4];
#pragma unroll
    for (int p = 0; p < 4; ++p)
#pragma unroll
        for (int c = 0; c < 4; ++c) acc[p][c] = 0ull;

    auto stage = [&](int ci_n, int bi) {
        const float* sp = src + (size_t)c_chidx[e][ci_n] * HW_;
        unsigned base = s_in_b + (unsigned)(bi * TILE * 4);
#pragma unroll
        for (int k = 0; k < 6; ++k) {
            int idx = tid + k * 256;
            if (k < 5 || tid < (TILE - 5 * 256))
                cpasync4(base + (unsigned)idx * 4u, sp + off[k], szb[k]);
        }
        cpasync_commit();
    };

    stage(0, 0);
    cpasync_wait_all();
    __syncthreads();

    for (int ci = 0; ci < CIN; ++ci) {
        if (ci + 1 < CIN) stage(ci + 1, (ci + 1) & 1);
        const float* cb = s_in + (ci & 1) * TILE;
        const float* wbase = s_w + ci * 25 * CO;
#pragma unroll
        for (int dx = 0; dx < 5; ++dx) {
            u64 dup[8];
#pragma unroll
            for (int j = 0; j < 8; ++j) {
                float v = cb[(ty * 4 + j) * 36 + tx + dx];
                dup[j] = pack2(v, v);
            }
#pragma unroll
            for (int dy = 0; dy < 5; ++dy) {
                const ulonglong2* wr =
                    reinterpret_cast<const ulonglong2*>(wbase + (dy * 5 + dx) * CO);
                ulonglong2 wp0 = wr[0], wp1 = wr[1];
#pragma unroll
                for (int p = 0; p < 4; ++p) {
                    ffma2(acc[p][0], dup[dy + p], wp0.x);
                    ffma2(acc[p][1], dup[dy + p], wp0.y);
                    ffma2(acc[p][2], dup[dy + p], wp1.x);
                    ffma2(acc[p][3], dup[dy + p], wp1.y);
                }
            }
        }
        if (ci + 1 < CIN) {
            cpasync_wait_all();
            __syncthreads();
        }
    }

    // epilogue -> split records (C=16: hi slots 0..7, lo slots 8..15)
    const int y0 = tile_y + ty * 4, x = tile_x + tx;
    uint32_t* ob = out + (size_t)b * 16384 * 16;
#pragma unroll
    for (int p = 0; p < 4; ++p) {
        uint32_t* op = ob + (size_t)((y0 + p) * 128 + x) * 16;
#pragma unroll
        for (int c = 0; c < 4; ++c) {
            float v0, v1;
            unpack2(acc[p][c], v0, v1);
            v0 = fmaxf(v0 + s_b[2 * c], 0.0f);
            v1 = fmaxf(v1 + s_b[2 * c + 1], 0.0f);
            uint32_t h0, l0, h1, l1;
            bf16split(v0, h0, l0);
            bf16split(v1, h1, l1);
            op[g * 4 + c]     = h0 | (h1 << 16);   // hi pair slot
            op[8 + g * 4 + c] = l0 | (l1 << 16);   // lo pair slot
        }
    }
}

// ---------------------------------------------------------------------------
// fused 1x1: 32 -> 128 (relu) -> 2, reads split records, writes fp32 output.
// ---------------------------------------------------------------------------
__global__ __launch_bounds__(256) void conv56(const uint32_t* __restrict__ in,
                                              const float* __restrict__ w5,
                                              const float* __restrict__ b5,
                                              const float* __restrict__ w6,
                                              const float* __restrict__ b6,
                                              float* __restrict__ out) {
    __shared__ __align__(16) u64 s_w5[128 * 32];
    __shared__ __align__(16) u64 s_w6[2 * 128];
    __shared__ float s_b5[128];

    const int tid = threadIdx.x;
    const int b   = blockIdx.y;
    const int px0 = blockIdx.x * 512 + tid;

    for (int i = tid; i < 128 * 32; i += 256) {
        float v = w5[i];
        s_w5[i] = pack2(v, v);
    }
    if (tid < 128) {
        float v0 = w6[tid], v1 = w6[128 + tid];
        s_w6[tid] = pack2(v0, v0);
        s_w6[128 + tid] = pack2(v1, v1);
        s_b5[tid] = b5[tid];
    }
    __syncthreads();

    const uint32_t* ra = in + ((size_t)b * 16384 + px0) * 32;
    const uint32_t* rb = in + ((size_t)b * 16384 + px0 + 256) * 32;
    u64 x2[32];
#pragma unroll
    for (int c2 = 0; c2 < 16; ++c2) {
        uint32_t hA = ra[c2], lA = ra[16 + c2];
        uint32_t hB = rb[c2], lB = rb[16 + c2];
        x2[2 * c2]     = pack2(blo16(hA) + blo16(lA), blo16(hB) + blo16(lB));
        x2[2 * c2 + 1] = pack2(bhi16(hA) + bhi16(lA), bhi16(hB) + bhi16(lB));
    }

    u64 acc0 = pack2(b6[0], b6[0]);
    u64 acc1 = pack2(b6[1], b6[1]);

    for (int j = 0; j < 128; ++j) {
        float bj = s_b5[j];
        u64 h = pack2(bj, bj);
        const ulonglong2* wr = reinterpret_cast<const ulonglong2*>(s_w5 + j * 32);
#pragma unroll
        for (int c2 = 0; c2 < 16; ++c2) {
            ulonglong2 wp = wr[c2];
            ffma2(h, x2[2 * c2], wp.x);
            ffma2(h, x2[2 * c2 + 1], wp.y);
        }
        float h0, h1;
        unpack2(h, h0, h1);
        u64 hr = pack2(fmaxf(h0, 0.0f), fmaxf(h1, 0.0f));
        ffma2(acc0, hr, s_w6[j]);
        ffma2(acc1, hr, s_w6[128 + j]);
    }

    float o00, o01, o10, o11;
    unpack2(acc0, o00, o01);
    unpack2(acc1, o10, o11);
    float* op = out + (size_t)b * 2 * HW_;
    op[px0] = o00;
    op[px0 + 256] = o01;
    op[HW_ + px0] = o10;
    op[HW_ + px0 + 256] = o11;
}

// ---------------------------------------------------------------------------
extern "C" void kernel_launch(void* const* d_in, const int* in_sizes, int n_in,
                              void* d_out, int out_size) {
    const float* x  = (const float*)d_in[0];
    const float* w0 = (const float*)d_in[2];
    const float* b0 = (const float*)d_in[3];
    const float* w1 = (const float*)d_in[4];
    const float* b1 = (const float*)d_in[5];
    const float* w2 = (const float*)d_in[6];
    const float* b2 = (const float*)d_in[7];
    const float* w3 = (const float*)d_in[8];
    const float* b3 = (const float*)d_in[9];
    const float* w4 = (const float*)d_in[10];
    const float* b4 = (const float*)d_in[11];
    const float* w5 = (const float*)d_in[12];
    const float* b5 = (const float*)d_in[13];
    const float* w6 = (const float*)d_in[14];
    const float* b6 = (const float*)d_in[15];

    uint32_t *bufA = nullptr, *bufB = nullptr;
    cudaGetSymbolAddress((void**)&bufA, g_bufA);
    cudaGetSymbolAddress((void**)&bufB, g_bufB);

    size_t smem0 = (size_t)(4 * 25 * 8 + 2 * 36 * 36 + 8) * 4;
    auto tsmem = [](int cin, int cout, int chunk) {
        int A = 8 * 132 * cin * 4;
        int Bb = chunk * 6 * cin * cout;          // 3 * (cout * 2*cin) per tap
        int scratch = 512 * (cout + 4) * 4;
        int bsz = Bb > scratch ? Bb : scratch;
        return (size_t)(1024 + A + bsz);
    };

    cudaFuncSetAttribute(conv0, cudaFuncAttributeMaxDynamicSharedMemorySize, (int)smem0);
    cudaFuncSetAttribute(tconv<16, 16, 25>, cudaFuncAttributeMaxDynamicSharedMemorySize,
                         (int)tsmem(16, 16, 25));
    cudaFuncSetAttribute(tconv<16, 32, 25>, cudaFuncAttributeMaxDynamicSharedMemorySize,
                         (int)tsmem(16, 32, 25));
    cudaFuncSetAttribute(tconv<32, 32, 13>, cudaFuncAttributeMaxDynamicSharedMemorySize,
                         (int)tsmem(32, 32, 13));

    dim3 blk2(256), blk5(512);
    conv0<<<dim3(16, 2, NB), blk2, smem0>>>(x, w0, b0, bufA);
    tconv<16, 16, 25><<<dim3(32, 1, NB), blk5, tsmem(16, 16, 25)>>>(bufA, w1, b1, bufB);
    tconv<16, 32, 25><<<dim3(32, 1, NB), blk5, tsmem(16, 32, 25)>>>(bufB, w2, b2, bufA);
    tconv<32, 32, 13><<<dim3(32, 1, NB), blk5, tsmem(32, 32, 13)>>>(bufA, w3, b3, bufB);
    tconv<32, 32, 13><<<dim3(32, 1, NB), blk5, tsmem(32, 32, 13)>>>(bufB, w4, b4, bufA);
    conv56<<<dim3(HW_ / 512, NB), blk2>>>(bufA, w5, b5, w6, b6, (float*)d_out);
}

// round 16
// speedup vs baseline: 2.0333x; 1.0043x over previous
#include <cuda_runtime.h>
#include <cstdint>

#define HW_ (128 * 128)
static constexpr int IMG = 128;
static constexpr int NB  = 304;
static constexpr size_t BUF_ELEMS = (size_t)NB * 32 * HW_;

// Activation records, C channels/pixel, C u32 per pixel:
//   u32 slots [0..C/2)  = bf16 hi pairs  (h[2c] | h[2c+1]<<16)
//   u32 slots [C/2..C)  = bf16 lo pairs  (l[2c] | l[2c+1]<<16)
// As a bf16[2C] K-vector: k in [0,C) = xh[k], k in [C,2C) = xl[k-C].
__device__ uint32_t g_bufA[BUF_ELEMS];
__device__ uint32_t g_bufB[BUF_ELEMS];

__constant__ int c_chidx[19][4] = {
    {1, 8, 19, 20}, {8, 9, 21, 22}, {9, 10, 23, 24}, {1, 11, 25, 26},
    {11, 12, 27, 28}, {12, 13, 29, 30}, {1, 2, 31, 32}, {2, 3, 33, 34},
    {3, 4, 35, 36}, {2, 16, 37, 38}, {1, 5, 39, 40}, {5, 6, 41, 42},
    {6, 7, 43, 44}, {5, 17, 45, 46}, {0, 1, 47, 48}, {0, 14, 49, 50},
    {0, 15, 51, 52}, {14, 16, 53, 54}, {15, 17, 55, 56}
};

typedef unsigned long long u64;

__device__ __forceinline__ u64 pack2(float lo, float hi) {
    u64 r; asm("mov.b64 %0, {%1, %2};" : "=l"(r) : "f"(lo), "f"(hi)); return r;
}
__device__ __forceinline__ void unpack2(u64 v, float& lo, float& hi) {
    asm("mov.b64 {%0, %1}, %2;" : "=f"(lo), "=f"(hi) : "l"(v));
}
__device__ __forceinline__ void ffma2(u64& d, u64 a, u64 b) {
    asm("fma.rn.f32x2 %0, %1, %2, %0;" : "+l"(d) : "l"(a), "l"(b));
}

// bf16 RNE split: v = hi_part + lo_part
__device__ __forceinline__ void bf16split(float v, uint32_t& hi, uint32_t& lo) {
    uint32_t ub = __float_as_uint(v);
    uint32_t hb = (ub + 0x7FFFu + ((ub >> 16) & 1u)) & 0xFFFF0000u;
    hi = hb >> 16;
    float lof = v - __uint_as_float(hb);
    uint32_t ul = __float_as_uint(lof);
    lo = (ul + 0x7FFFu + ((ul >> 16) & 1u)) >> 16;
}
__device__ __forceinline__ float blo16(uint32_t u) { return __uint_as_float(u << 16); }
__device__ __forceinline__ float bhi16(uint32_t u) {
    return __uint_as_float(u & 0xFFFF0000u);
}

__device__ __forceinline__ void cpasync16(unsigned dst, const void* src, int sz) {
    asm volatile("cp.async.cg.shared.global [%0], [%1], 16, %2;"
                 :: "r"(dst), "l"(src), "r"(sz));
}
__device__ __forceinline__ void cpasync4(unsigned dst, const float* src, int sz) {
    asm volatile("cp.async.ca.shared.global [%0], [%1], 4, %2;"
                 :: "r"(dst), "l"(src), "r"(sz));
}
__device__ __forceinline__ void cpasync_commit() { asm volatile("cp.async.commit_group;"); }
__device__ __forceinline__ void cpasync_wait_all() {
    asm volatile("cp.async.wait_group 0;" ::: "memory");
}

#define SMEM_SWZ(off) ((off) ^ (((off) >> 3) & 0x70))

__device__ __forceinline__ uint32_t smem_u32(const void* p) {
    uint32_t a;
    asm("{ .reg .u64 t; cvta.to.shared.u64 t, %1; cvt.u32.u64 %0, t; }" : "=r"(a) : "l"(p));
    return a;
}
// ldmatrix x4 (baseline PTX, sm_75+)
__device__ __forceinline__ void ldsm4(uint32_t* r, uint32_t addr) {
    asm volatile("ldmatrix.sync.aligned.m8n8.x4.shared.b16 {%0,%1,%2,%3}, [%4];"
                 : "=r"(r[0]), "=r"(r[1]), "=r"(r[2]), "=r"(r[3]) : "r"(addr));
}
// mma.sync bf16 (baseline PTX, sm_80+) -> HMMA
__device__ __forceinline__ void mma_bf16(float* c, const uint32_t* a,
                                         uint32_t b0, uint32_t b1) {
    asm volatile(
        "mma.sync.aligned.m16n8k16.row.col.f32.bf16.bf16.f32 "
        "{%0,%1,%2,%3}, {%4,%5,%6,%7}, {%8,%9}, {%0,%1,%2,%3};"
        : "+f"(c[0]), "+f"(c[1]), "+f"(c[2]), "+f"(c[3])
        : "r"(a[0]), "r"(a[1]), "r"(a[2]), "r"(a[3]), "r"(b0), "r"(b1));
}

// One shared declaration for every dynamic-smem kernel in this TU.
extern __shared__ __align__(1024) unsigned char dynsmem[];

// ---------------------------------------------------------------------------
// HMMA 5x5 conv + relu.  Grid (32 row-quads, 1, NB), 512 thr (16 warps).
// CTA: 4 output rows x 128 px (M=512) x COUT.  Warp: 32 px (2 m16 frags).
// Split-record scheme: main pass xh*wh over K=CIN; corr pass (xh*wl + xl*wh)
// over K=2*CIN with B = [wl | wh].  3*CIN total K-work.
// SOFTWARE PIPELINED: all A fragments for a tap loaded up-front (latency
// hidden under previous tap's MMA drain); B fragments double-buffered across
// kc so every B load is covered by a full MMA block.
// ---------------------------------------------------------------------------
template <int CIN, int COUT, int CHUNK>
__global__ __launch_bounds__(512, 1)
void tconv(const uint32_t* __restrict__ in_rec, const float* __restrict__ w,
           const float* __restrict__ bias, uint32_t* __restrict__ out_rec) {
    constexpr int RECB = CIN * 4;                 // bytes per input record
    constexpr int KBM  = CIN * 2;                 // main B row bytes (K=CIN)
    constexpr int KBC  = CIN * 4;                 // corr B row bytes (K=2CIN)
    constexpr int KS2  = CIN / 8;                 // corr K-steps
    constexpr int KSM  = CIN / 16;                // main K-steps
    constexpr int NG   = COUT / 8;                // 8-wide n-groups
    constexpr int MAINB = COUT * KBM;             // main block bytes (512B mult.)
    constexpr int TAPB  = 3 * MAINB;              // per-tap block bytes
    constexpr int A_OFF = 1024;
    constexpr int A_BYTES = 8 * 132 * RECB;       // multiple of 1024
    constexpr int B_OFF = A_OFF + A_BYTES;
    constexpr int U = RECB / 16;                  // 16B units per record

    unsigned char* smem = dynsmem;
    const uint32_t sb = smem_u32(smem);
    const int tid  = threadIdx.x;
    const int wnum = tid >> 5;
    const int lane = tid & 31;
    const int y0   = blockIdx.x * 4;
    const int b    = blockIdx.z;
    const size_t img = (size_t)b * 16384;

    if (tid < COUT) ((float*)smem)[tid] = bias[tid];

    // ---- stage A: rows y0-2..y0+5, 132 px, zfill halo ----
    {
        constexpr int TOT = 8 * 132 * U;
        for (int idx = tid; idx < TOT; idx += 512) {
            int pix = idx / U, u = idx - pix * U;
            int row = pix / 132, xc = pix - row * 132;
            int y = y0 - 2 + row, x = xc - 2;
            bool v = ((unsigned)y < 128u) & ((unsigned)x < 128u);
            const char* src =
                (const char*)(in_rec + (img + (v ? (size_t)(y * 128 + x) : 0)) * CIN) + u * 16;
            unsigned rel = (unsigned)(pix * RECB + u * 16);
            cpasync16(sb + A_OFF + SMEM_SWZ(rel), src, v ? 16 : 0);
        }
        cpasync_commit();
    }

    // per-thread ldmatrix address components (validated R13/R14)
    const int a_px = ((lane >> 3) & 1) * 8 + (lane & 7);
    const int a_kb = (lane >> 4) * 16;
    const int b_n  = ((lane >> 4) & 1) * 8 + (lane & 7);
    const int b_kb = ((lane >> 3) & 1) * 16;
    const int wrow = wnum >> 2;           // output row within quad (0..3)
    const int wcol = (wnum & 3) * 32;     // x-base of this warp's 32 px

    float acc[2][NG][4];
#pragma unroll
    for (int f = 0; f < 2; ++f)
#pragma unroll
        for (int g = 0; g < NG; ++g)
#pragma unroll
            for (int i = 0; i < 4; ++i) acc[f][g][i] = 0.0f;

    const uint32_t sbA = sb + A_OFF;
    const uint32_t sbB = sb + B_OFF;

    bool firstA = true;
#pragma unroll 1
    for (int t0 = 0; t0 < 25; t0 += CHUNK) {
        const int nt = (25 - t0 < CHUNK) ? (25 - t0) : CHUNK;
        if (t0) __syncthreads();          // previous chunk's compute done with B

        // stage B chunk: main (wh pairs) + corr ([wl | wh])
        {
            const int tot = nt * COUT * (CIN / 2);
            for (int i = tid; i < tot; i += 512) {
                int c  = i % (CIN / 2);                 // u32 pair index
                int co = (i / (CIN / 2)) % COUT;
                int tl = i / ((CIN / 2) * COUT);
                int tap = t0 + tl;
                float wv0 = w[((size_t)co * CIN + 2 * c) * 25 + tap];
                float wv1 = w[((size_t)co * CIN + 2 * c + 1) * 25 + tap];
                uint32_t h0, l0, h1, l1;
                bf16split(wv0, h0, l0);
                bf16split(wv1, h1, l1);
                uint32_t hp = h0 | (h1 << 16);
                uint32_t lp = l0 | (l1 << 16);
                unsigned tb = (unsigned)(tl * TAPB);
                // main: row co, slot c
                *(uint32_t*)(smem + B_OFF +
                    SMEM_SWZ(tb + (unsigned)(co * KBM + c * 4))) = hp;
                // corr: row co; k<CIN -> wl pairs; k>=CIN -> wh pairs
                unsigned cb = tb + (unsigned)MAINB + (unsigned)(co * KBC);
                *(uint32_t*)(smem + B_OFF + SMEM_SWZ(cb + (unsigned)(c * 4))) = lp;
                *(uint32_t*)(smem + B_OFF +
                    SMEM_SWZ(cb + (unsigned)((CIN / 2 + c) * 4))) = hp;
            }
        }
        if (firstA) { cpasync_wait_all(); firstA = false; }
        __syncthreads();

#pragma unroll 1
        for (int tl = 0; tl < nt; ++tl) {
            const int tap = t0 + tl;
            const int dy = tap / 5, dx = tap - dy * 5;
            unsigned abase =
                (unsigned)(((wrow + dy) * 132 + wcol + dx + a_px) * RECB + a_kb);
            unsigned mainB = (unsigned)(tl * TAPB) + (unsigned)(b_n * KBM) + b_kb;
            unsigned corrB = (unsigned)(tl * TAPB + MAINB) +
                             (unsigned)(b_n * KBC) + b_kb;

            // ---- all A fragments for this tap (issue under prior MMA drain)
            uint32_t A0[KS2][4], A1[KS2][4];
#pragma unroll
            for (int kc = 0; kc < KS2; ++kc) {
                ldsm4(A0[kc], sbA + SMEM_SWZ(abase + kc * 32));
                ldsm4(A1[kc], sbA + SMEM_SWZ(abase + 16 * RECB + kc * 32));
            }

            // ---- B fragments, double-buffered across kc
            uint32_t bc[2][NG / 2][4];
            uint32_t bm[2][NG / 2][4];
#pragma unroll
            for (int gp = 0; gp < NG / 2; ++gp)
                ldsm4(bc[0][gp], sbB + SMEM_SWZ(corrB + gp * 16 * KBC));
#pragma unroll
            for (int gp = 0; gp < NG / 2; ++gp)
                ldsm4(bm[0][gp], sbB + SMEM_SWZ(mainB + gp * 16 * KBM));

#pragma unroll
            for (int kc = 0; kc < KS2; ++kc) {
                const int cur = kc & 1, nxt = cur ^ 1;
                if (kc + 1 < KS2) {
#pragma unroll
                    for (int gp = 0; gp < NG / 2; ++gp)
                        ldsm4(bc[nxt][gp],
                              sbB + SMEM_SWZ(corrB + gp * 16 * KBC + (kc + 1) * 32));
                    if (kc + 1 < KSM) {
#pragma unroll
                        for (int gp = 0; gp < NG / 2; ++gp)
                            ldsm4(bm[nxt][gp],
                                  sbB + SMEM_SWZ(mainB + gp * 16 * KBM + (kc + 1) * 32));
                    }
                }
                // corr pass: B = [wl | wh], K=2*CIN
#pragma unroll
                for (int g = 0; g < NG; ++g) {
                    uint32_t p0 = bc[cur][g >> 1][(g & 1) * 2];
                    uint32_t p1 = bc[cur][g >> 1][(g & 1) * 2 + 1];
                    mma_bf16(acc[0][g], A0[kc], p0, p1);
                    mma_bf16(acc[1][g], A1[kc], p0, p1);
                }
                // main pass: B = wh, K=CIN (shares A fragments)
                if (kc < KSM) {
#pragma unroll
                    for (int g = 0; g < NG; ++g) {
                        uint32_t p0 = bm[cur][g >> 1][(g & 1) * 2];
                        uint32_t p1 = bm[cur][g >> 1][(g & 1) * 2 + 1];
                        mma_bf16(acc[0][g], A0[kc], p0, p1);
                        mma_bf16(acc[1][g], A1[kc], p0, p1);
                    }
                }
            }
        }
    }

    __syncthreads();                      // before reusing B region as scratch

    // ---- epilogue: +bias, relu, split-pack, smem transpose, coalesced out ----
    {
        const float* sbias = (const float*)smem;
        uint32_t* so = (uint32_t*)(smem + B_OFF);
        constexpr int STR = COUT + 4;     // u32 stride, keeps 16B px alignment
#pragma unroll
        for (int f = 0; f < 2; ++f) {
            int px = wrow * 128 + wcol + f * 16 + (lane >> 2);
#pragma unroll
            for (int g = 0; g < NG; ++g) {
                int co = g * 8 + (lane & 3) * 2;      // channel pair (co, co+1)
                float v0 = fmaxf(acc[f][g][0] + sbias[co], 0.0f);
                float v1 = fmaxf(acc[f][g][1] + sbias[co + 1], 0.0f);
                float v2 = fmaxf(acc[f][g][2] + sbias[co], 0.0f);
                float v3 = fmaxf(acc[f][g][3] + sbias[co + 1], 0.0f);
                uint32_t h0, l0, h1, l1;
                bf16split(v0, h0, l0);
                bf16split(v1, h1, l1);
                so[px * STR + (co >> 1)]            = h0 | (h1 << 16);
                so[px * STR + COUT / 2 + (co >> 1)] = l0 | (l1 << 16);
                bf16split(v2, h0, l0);
                bf16split(v3, h1, l1);
                so[(px + 8) * STR + (co >> 1)]            = h0 | (h1 << 16);
                so[(px + 8) * STR + COUT / 2 + (co >> 1)] = l0 | (l1 << 16);
            }
        }
        __syncthreads();

        constexpr int CH = COUT / 4;      // uint4 chunks per pixel
        const int u  = tid & (CH - 1);
        const int pb = tid / CH;
#pragma unroll
        for (int p = pb; p < 512; p += 512 / CH) {
            uint4 val;
            val.x = so[p * STR + u * 4 + 0];
            val.y = so[p * STR + u * 4 + 1];
            val.z = so[p * STR + u * 4 + 2];
            val.w = so[p * STR + u * 4 + 3];
            int y = y0 + (p >> 7), x = p & 127;
            *(uint4*)(out_rec + (img + (size_t)y * 128 + x) * COUT + u * 4) = val;
        }
    }
}

// ---------------------------------------------------------------------------
// Layer 0: FFMA2 5x5 conv with gather (4 -> 16), writes split records.
// ---------------------------------------------------------------------------
__global__ __launch_bounds__(256, 3) void conv0(const float* __restrict__ in,
                                                const float* __restrict__ w,
                                                const float* __restrict__ bias,
                                                uint32_t* __restrict__ out) {
    constexpr int CIN = 4, CO = 8;
    constexpr int SW_SZ = CIN * 25 * CO;
    constexpr int TILE  = 36 * 36;
    float* smem = (float*)dynsmem;
    float* s_w  = smem;
    float* s_in = smem + SW_SZ;
    float* s_b  = s_in + 2 * TILE;

    const int tid = threadIdx.x;
    const int tile = blockIdx.x, g = blockIdx.y, b = blockIdx.z;
    const int tile_x = (tile & 3) * 32, tile_y = (tile >> 2) * 32;

    for (int idx = tid; idx < SW_SZ; idx += 256) {
        int co = idx & 7, r = idx >> 3;
        int ci = r / 25, tap = r % 25;
        s_w[idx] = w[((size_t)(g * CO + co) * CIN + ci) * 25 + tap];
    }
    if (tid < CO) s_b[tid] = bias[g * CO + tid];

    int n = b / 19, e = b - n * 19;
    const float* src = in + (size_t)n * 57 * HW_;

    int off[6], szb[6];
#pragma unroll
    for (int k = 0; k < 6; ++k) {
        int idx = tid + k * 256;
        int r = idx / 36, c = idx - r * 36;
        int ih = tile_y + r - 2, iw = tile_x + c - 2;
        bool v = ((unsigned)ih < 128u) && ((unsigned)iw < 128u);
        szb[k] = v ? 4 : 0;
        off[k] = v ? (ih * IMG + iw) : 0;
    }

    const unsigned s_in_b = (unsigned)__cvta_generic_to_shared(s_in);
    const int tx = tid & 31, ty = tid >> 5;

    u64 acc[4][4];
#pragma unroll
    for (int p = 0; p < 4; ++p)
#pragma unroll
        for (int c = 0; c < 4; ++c) acc[p][c] = 0ull;

    auto stage = [&](int ci_n, int bi) {
        const float* sp = src + (size_t)c_chidx[e][ci_n] * HW_;
        unsigned base = s_in_b + (unsigned)(bi * TILE * 4);
#pragma unroll
        for (int k = 0; k < 6; ++k) {
            int idx = tid + k * 256;
            if (k < 5 || tid < (TILE - 5 * 256))
                cpasync4(base + (unsigned)idx * 4u, sp + off[k], szb[k]);
        }
        cpasync_commit();
    };

    stage(0, 0);
    cpasync_wait_all();
    __syncthreads();

    for (int ci = 0; ci < CIN; ++ci) {
        if (ci + 1 < CIN) stage(ci + 1, (ci + 1) & 1);
        const float* cb = s_in + (ci & 1) * TILE;
        const float* wbase = s_w + ci * 25 * CO;
#pragma unroll
        for (int dx = 0; dx < 5; ++dx) {
            u64 dup[8];
#pragma unroll
            for (int j = 0; j < 8; ++j) {
                float v = cb[(ty * 4 + j) * 36 + tx + dx];
                dup[j] = pack2(v, v);
            }
#pragma unroll
            for (int dy = 0; dy < 5; ++dy) {
                const ulonglong2* wr =
                    reinterpret_cast<const ulonglong2*>(wbase + (dy * 5 + dx) * CO);
                ulonglong2 wp0 = wr[0], wp1 = wr[1];
#pragma unroll
                for (int p = 0; p < 4; ++p) {
                    ffma2(acc[p][0], dup[dy + p], wp0.x);
                    ffma2(acc[p][1], dup[dy + p], wp0.y);
                    ffma2(acc[p][2], dup[dy + p], wp1.x);
                    ffma2(acc[p][3], dup[dy + p], wp1.y);
                }
            }
        }
        if (ci + 1 < CIN) {
            cpasync_wait_all();
            __syncthreads();
        }
    }

    // epilogue -> split records (C=16: hi slots 0..7, lo slots 8..15)
    const int y0 = tile_y + ty * 4, x = tile_x + tx;
    uint32_t* ob = out + (size_t)b * 16384 * 16;
#pragma unroll
    for (int p = 0; p < 4; ++p) {
        uint32_t* op = ob + (size_t)((y0 + p) * 128 + x) * 16;
#pragma unroll
        for (int c = 0; c < 4; ++c) {
            float v0, v1;
            unpack2(acc[p][c], v0, v1);
            v0 = fmaxf(v0 + s_b[2 * c], 0.0f);
            v1 = fmaxf(v1 + s_b[2 * c + 1], 0.0f);
            uint32_t h0, l0, h1, l1;
            bf16split(v0, h0, l0);
            bf16split(v1, h1, l1);
            op[g * 4 + c]     = h0 | (h1 << 16);   // hi pair slot
            op[8 + g * 4 + c] = l0 | (l1 << 16);   // lo pair slot
        }
    }
}

// ---------------------------------------------------------------------------
// fused 1x1: 32 -> 128 (relu) -> 2, reads split records, writes fp32 output.
// ---------------------------------------------------------------------------
__global__ __launch_bounds__(256) void conv56(const uint32_t* __restrict__ in,
                                              const float* __restrict__ w5,
                                              const float* __restrict__ b5,
                                              const float* __restrict__ w6,
                                              const float* __restrict__ b6,
                                              float* __restrict__ out) {
    __shared__ __align__(16) u64 s_w5[128 * 32];
    __shared__ __align__(16) u64 s_w6[2 * 128];
    __shared__ float s_b5[128];

    const int tid = threadIdx.x;
    const int b   = blockIdx.y;
    const int px0 = blockIdx.x * 512 + tid;

    for (int i = tid; i < 128 * 32; i += 256) {
        float v = w5[i];
        s_w5[i] = pack2(v, v);
    }
    if (tid < 128) {
        float v0 = w6[tid], v1 = w6[128 + tid];
        s_w6[tid] = pack2(v0, v0);
        s_w6[128 + tid] = pack2(v1, v1);
        s_b5[tid] = b5[tid];
    }
    __syncthreads();

    const uint32_t* ra = in + ((size_t)b * 16384 + px0) * 32;
    const uint32_t* rb = in + ((size_t)b * 16384 + px0 + 256) * 32;
    u64 x2[32];
#pragma unroll
    for (int c2 = 0; c2 < 16; ++c2) {
        uint32_t hA = ra[c2], lA = ra[16 + c2];
        uint32_t hB = rb[c2], lB = rb[16 + c2];
        x2[2 * c2]     = pack2(blo16(hA) + blo16(lA), blo16(hB) + blo16(lB));
        x2[2 * c2 + 1] = pack2(bhi16(hA) + bhi16(lA), bhi16(hB) + bhi16(lB));
    }

    u64 acc0 = pack2(b6[0], b6[0]);
    u64 acc1 = pack2(b6[1], b6[1]);

    for (int j = 0; j < 128; ++j) {
        float bj = s_b5[j];
        u64 h = pack2(bj, bj);
        const ulonglong2* wr = reinterpret_cast<const ulonglong2*>(s_w5 + j * 32);
#pragma unroll
        for (int c2 = 0; c2 < 16; ++c2) {
            ulonglong2 wp = wr[c2];
            ffma2(h, x2[2 * c2], wp.x);
            ffma2(h, x2[2 * c2 + 1], wp.y);
        }
        float h0, h1;
        unpack2(h, h0, h1);
        u64 hr = pack2(fmaxf(h0, 0.0f), fmaxf(h1, 0.0f));
        ffma2(acc0, hr, s_w6[j]);
        ffma2(acc1, hr, s_w6[128 + j]);
    }

    float o00, o01, o10, o11;
    unpack2(acc0, o00, o01);
    unpack2(acc1, o10, o11);
    float* op = out + (size_t)b * 2 * HW_;
    op[px0] = o00;
    op[px0 + 256] = o01;
    op[HW_ + px0] = o10;
    op[HW_ + px0 + 256] = o11;
}

// ---------------------------------------------------------------------------
extern "C" void kernel_launch(void* const* d_in, const int* in_sizes, int n_in,
                              void* d_out, int out_size) {
    const float* x  = (const float*)d_in[0];
    const float* w0 = (const float*)d_in[2];
    const float* b0 = (const float*)d_in[3];
    const float* w1 = (const float*)d_in[4];
    const float* b1 = (const float*)d_in[5];
    const float* w2 = (const float*)d_in[6];
    const float* b2 = (const float*)d_in[7];
    const float* w3 = (const float*)d_in[8];
    const float* b3 = (const float*)d_in[9];
    const float* w4 = (const float*)d_in[10];
    const float* b4 = (const float*)d_in[11];
    const float* w5 = (const float*)d_in[12];
    const float* b5 = (const float*)d_in[13];
    const float* w6 = (const float*)d_in[14];
    const float* b6 = (const float*)d_in[15];

    uint32_t *bufA = nullptr, *bufB = nullptr;
    cudaGetSymbolAddress((void**)&bufA, g_bufA);
    cudaGetSymbolAddress((void**)&bufB, g_bufB);

    size_t smem0 = (size_t)(4 * 25 * 8 + 2 * 36 * 36 + 8) * 4;
    auto tsmem = [](int cin, int cout, int chunk) {
        int A = 8 * 132 * cin * 4;
        int Bb = chunk * 6 * cin * cout;          // 3 * (cout * 2*cin) per tap
        int scratch = 512 * (cout + 4) * 4;
        int bsz = Bb > scratch ? Bb : scratch;
        return (size_t)(1024 + A + bsz);
    };

    cudaFuncSetAttribute(conv0, cudaFuncAttributeMaxDynamicSharedMemorySize, (int)smem0);
    cudaFuncSetAttribute(tconv<16, 16, 25>, cudaFuncAttributeMaxDynamicSharedMemorySize,
                         (int)tsmem(16, 16, 25));
    cudaFuncSetAttribute(tconv<16, 32, 25>, cudaFuncAttributeMaxDynamicSharedMemorySize,
                         (int)tsmem(16, 32, 25));
    cudaFuncSetAttribute(tconv<32, 32, 13>, cudaFuncAttributeMaxDynamicSharedMemorySize,
                         (int)tsmem(32, 32, 13));

    dim3 blk2(256), blk5(512);
    conv0<<<dim3(16, 2, NB), blk2, smem0>>>(x, w0, b0, bufA);
    tconv<16, 16, 25><<<dim3(32, 1, NB), blk5, tsmem(16, 16, 25)>>>(bufA, w1, b1, bufB);
    tconv<16, 32, 25><<<dim3(32, 1, NB), blk5, tsmem(16, 32, 25)>>>(bufB, w2, b2, bufA);
    tconv<32, 32, 13><<<dim3(32, 1, NB), blk5, tsmem(32, 32, 13)>>>(bufA, w3, b3, bufB);
    tconv<32, 32, 13><<<dim3(32, 1, NB), blk5, tsmem(32, 32, 13)>>>(bufB, w4, b4, bufA);
    conv56<<<dim3(HW_ / 512, NB), blk2>>>(bufA, w5, b5, w6, b6, (float*)d_out);
}